// round 11
// baseline (speedup 1.0000x reference)
#include <cuda_runtime.h>
#include <cuda_fp16.h>
#include <cstdint>

// ---------------------------------------------------------------------------
// Problem constants
// ---------------------------------------------------------------------------
#define M_TOK   64
#define KDIM    8192
#define NOUT    14336
#define KW      (KDIM / 2)          // 4096 int32 per output row
#define NTILE   128
#define GRID_N  (NOUT / NTILE)      // 112 CTAs = one wave

// SMEM: weight ring 6 x 16KB (one half-chunk = 64 k x 128 rows each),
//       x ring 4 x 16KB (one iteration = 128 k each). Total 160KB.
#define WSTAGES 6
#define WSTAGE  16384
#define XOFF    (WSTAGES * WSTAGE)  // 98304
#define XSTAGE  16384
#define SMEM_TOTAL (XOFF + 4 * XSTAGE)  // 163840

// x (fp16, k-permuted + bank-swizzled) staged per 64-k chunk: 128 chunks x 8KB
__device__ __align__(16) unsigned char g_ximg[(size_t)M_TOK * KDIM * 2];  // 1 MB

// ---------------------------------------------------------------------------
// Helpers
// ---------------------------------------------------------------------------
__device__ __forceinline__ void cp16(uint32_t saddr, const void* g) {
    asm volatile("cp.async.cg.shared.global [%0], [%1], 16;" :: "r"(saddr), "l"(g));
}
__device__ __forceinline__ void cp_commit() {
    asm volatile("cp.async.commit_group;" ::: "memory");
}
__device__ __forceinline__ uint2 lds64(uint32_t addr) {
    uint2 r;
    asm volatile("ld.shared.v2.u32 {%0,%1}, [%2];" : "=r"(r.x), "=r"(r.y) : "r"(addr));
    return r;
}
__device__ __forceinline__ uint4 lds128(uint32_t addr) {
    uint4 r;
    asm volatile("ld.shared.v4.u32 {%0,%1,%2,%3}, [%4];"
                 : "=r"(r.x), "=r"(r.y), "=r"(r.z), "=r"(r.w) : "r"(addr));
    return r;
}
__device__ __forceinline__ void mma16816(float* d, uint32_t a0, uint32_t a1,
                                         uint32_t a2, uint32_t a3,
                                         uint32_t b0, uint32_t b1) {
    asm volatile(
        "mma.sync.aligned.m16n8k16.row.col.f32.f16.f16.f32 "
        "{%0,%1,%2,%3}, {%4,%5,%6,%7}, {%8,%9}, {%0,%1,%2,%3};"
        : "+f"(d[0]), "+f"(d[1]), "+f"(d[2]), "+f"(d[3])
        : "r"(a0), "r"(a1), "r"(a2), "r"(a3), "r"(b0), "r"(b1));
}

// int4-pair dequant: one int32 (value 0..255; lo nibble = even k) -> f16x2 {qlo,qhi}.
// lo half = 0x6408 ^ nibLo = 1032 + qlo (exact); HSUB2 by 1032 -> exact signed int4.
__device__ __forceinline__ uint32_t dq2(uint32_t v) {
    uint32_t t = (v & 0xFu) ^ 0x64086408u;
    uint32_t p = t ^ ((v << 12) & 0x000F0000u);
    __half2 hp = *reinterpret_cast<__half2*>(&p);
    __half2 r = __hsub2(hp, __half2half2(__ushort_as_half((unsigned short)0x6408)));
    return *reinterpret_cast<uint32_t*>(&r);
}

// ---------------------------------------------------------------------------
// Pre-kernel: x [64,8192] f32 -> f16 with the k-permutation + LDS swizzle baked in.
// Chunk cc covers physical k [cc*64, cc*64+64). Granule q (q = 4c+s, c=q>>2, s=q&3)
// stores 4 halves = physical k {8c+2s, 8c+2s+1, 32+8c+2s, 33+8c+2s} at byte offset
// tok*128 + ((q ^ (tok&7)) * 8) inside the 8KB chunk tile.
// ---------------------------------------------------------------------------
__global__ void convert_x(const float* __restrict__ x) {
    int tg  = blockIdx.x * 256 + threadIdx.x;    // 131072 threads
    int cc  = tg >> 10;
    int rem = tg & 1023;
    int tok = rem >> 4;
    int q   = rem & 15;
    int c = q >> 2, s = q & 3;
    int k0 = cc * 64 + 8 * c + 2 * s;
    float2 v0 = *reinterpret_cast<const float2*>(x + (size_t)tok * KDIM + k0);
    float2 v1 = *reinterpret_cast<const float2*>(x + (size_t)tok * KDIM + k0 + 32);
    __half2 h0 = __floats2half2_rn(v0.x, v0.y);
    __half2 h1 = __floats2half2_rn(v1.x, v1.y);
    uint2 st;
    st.x = *reinterpret_cast<uint32_t*>(&h0);
    st.y = *reinterpret_cast<uint32_t*>(&h1);
    *reinterpret_cast<uint2*>(g_ximg + (size_t)cc * 8192 + tok * 128 +
                              ((q ^ (tok & 7)) << 3)) = st;
}

// ---------------------------------------------------------------------------
// Main kernel: CTA = 128 out-rows x 64 tokens, 512 threads / 16 warps in an
// 8(row) x 2(token) grid; warp tile = 16 rows x 32 tokens. K loop over 128
// half-chunks (64 k each). Both weights and x flow through cp.async SMEM
// rings; per-SM DRAM throughput is outstanding-request limited PER WARP, so
// 16 memory-issuing warps (vs 8) is the bandwidth lever. Registers stay ~95
// (weights never in regs), avoiding the R5 512-thread register collapse.
//
// Weight stage layout: row r (0..127) at r*128; 16B granule g (int32s 4g..4g+3
// of the half-chunk) stored at (g ^ sw(r))*16, sw(r)=((r&1)<<2)|((r>>1)&3).
// sw is a bijection on 0..7 -> STS phases (8 rows, same g) conflict-free;
// sw(2k)^sw(2k+1)=4 -> LDS.128 phases (rows rl,rl+1 x cl 0..3) conflict-free.
// All swizzle XORs are applied to pure byte OFFSETS; sb is added last.
// ---------------------------------------------------------------------------
__global__ __launch_bounds__(512, 1)
void qmain(const int* __restrict__ wp, const float* __restrict__ ws,
           const float* __restrict__ bias, float* __restrict__ out) {
    extern __shared__ __align__(16) unsigned char smem[];

    const int tid  = threadIdx.x;
    const int lane = tid & 31, warp = tid >> 5;       // warp 0..15
    const int wr = warp >> 1, wt = warp & 1;          // wr 0..7 rows, wt 0..1 tokens
    const int rl = lane >> 2, cl = lane & 3;
    const int r0 = blockIdx.x * NTILE;

    const uint32_t sb = (uint32_t)__cvta_generic_to_shared(smem);

    // ---- weight STS side: thread covers row (tid&127), granules 2*gset+{0,1} ----
    const int srow = tid & 127;
    const int sgb  = (tid >> 7) * 2;                  // gset*2: granules sgb, sgb+1
    const uint32_t swr = ((uint32_t)(srow & 1) << 2) | (((uint32_t)srow >> 1) & 3);
    const int* wsrc = wp + (size_t)(r0 + srow) * KW;   // + h*32 + (sgb+i)*4
    uint32_t wdst[2];                                   // offsets within a stage
#pragma unroll
    for (int i = 0; i < 2; i++)
        wdst[i] = (uint32_t)srow * 128 + ((((uint32_t)(sgb + i)) ^ swr) << 4);

    // ---- weight LDS side: rows wr*16 + rh*8 + rl; granules cl and cl^4 ----
    const uint32_t swl = ((uint32_t)(rl & 1) << 2) | (((uint32_t)rl >> 1) & 3);
    uint32_t wlo[2];                                    // offsets within a stage
#pragma unroll
    for (int rh = 0; rh < 2; rh++)
        wlo[rh] = (uint32_t)(wr * 16 + rh * 8 + rl) * 128 +
                  (((uint32_t)cl ^ swl) << 4);

    // ---- x fragment addresses: token = wt*32 + nt*8 + rl; granule (4cl+s)^rl ----
    uint32_t baddr[4];
#pragma unroll
    for (int nt = 0; nt < 4; nt++)
        baddr[nt] = sb + XOFF + (uint32_t)(wt * 32 + nt * 8 + rl) * 128;
    uint32_t gq[4];
#pragma unroll
    for (int s = 0; s < 4; s++)
        gq[s] = (uint32_t)(((4 * cl + s) ^ rl) << 3);

#define ISSUE_W(h_, slot_) do {                                                 \
        if ((h_) < 128) {                                                       \
            const uint32_t so_ = sb + (uint32_t)(slot_) * WSTAGE;               \
            const int* ws_ = wsrc + (h_) * 32 + sgb * 4;                        \
            cp16(so_ + wdst[0], ws_);                                           \
            cp16(so_ + wdst[1], ws_ + 4);                                       \
        } } while (0)

#define ISSUE_X(it_, slot_) do {                                               \
        const unsigned char* xg_ = g_ximg + (size_t)(it_) * 16384 + tid * 32;  \
        const uint32_t xd_ = sb + XOFF + (uint32_t)(slot_) * XSTAGE +          \
                             (uint32_t)tid * 32;                               \
        cp16(xd_, xg_);  cp16(xd_ + 16, xg_ + 16);                             \
    } while (0)

#define COMP4(u4, s_) ((s_) == 0 ? (u4).x : (s_) == 1 ? (u4).y : (s_) == 2 ? (u4).z : (u4).w)

// sx_ is an offset RELATIVE to the x region; baddr already has sb+XOFF.
#define COMPUTE(W, sx_) do {                                                    \
        _Pragma("unroll")                                                       \
        for (int s_ = 0; s_ < 4; s_++) {                                        \
            uint32_t a0 = dq2(COMP4(W[0][0], s_));                              \
            uint32_t a1 = dq2(COMP4(W[1][0], s_));                              \
            uint32_t a2 = dq2(COMP4(W[0][1], s_));                              \
            uint32_t a3 = dq2(COMP4(W[1][1], s_));                              \
            _Pragma("unroll")                                                   \
            for (int nt_ = 0; nt_ < 4; nt_++) {                                 \
                uint2 b_ = lds64(baddr[nt_] + (sx_) + gq[s_]);                  \
                mma16816(d[nt_], a0, a1, a2, a3, b_.x, b_.y);                   \
            }                                                                   \
        } } while (0)

    float d[4][4] = {};

    // Prologue: weight halves 0..4 + x iterations 0..2 in flight (5 groups)
    ISSUE_W(0, 0); ISSUE_X(0, 0); cp_commit();
    ISSUE_W(1, 1); ISSUE_X(1, 1); cp_commit();
    ISSUE_W(2, 2); ISSUE_X(2, 2); cp_commit();
    ISSUE_W(3, 3); cp_commit();
    ISSUE_W(4, 4); cp_commit();

    int scur = 0;   // slot of half h
    int s5   = 5;   // slot of half h+5
    for (int h = 0; h < 128; h++) {
        asm volatile("cp.async.wait_group 4;" ::: "memory");
        __syncthreads();   // visibility of other threads' cp.async fills

        // Load this half's weight fragments from SMEM (conflict-free LDS.128)
        uint4 W[2][2];
        {
            const uint32_t so = sb + (uint32_t)scur * WSTAGE;
#pragma unroll
            for (int rh = 0; rh < 2; rh++) {
                W[rh][0] = lds128(so + wlo[rh]);
                W[rh][1] = lds128(so + (wlo[rh] ^ 64u));  // XOR on offset only
            }
        }
        const uint32_t sx = (uint32_t)((h >> 1) & 3) * XSTAGE +
                            (uint32_t)(h & 1) * 8192u;
        COMPUTE(W, sx);

        // Refill: W(h+5) into slot (h-1)%6 (its readers finished before the
        // barrier above); x(j+3) at even halves into slot (j+3)&3.
        ISSUE_W(h + 5, s5);
        if (!(h & 1)) {
            const int jn = (h >> 1) + 3;
            if (jn < 64) ISSUE_X(jn, jn & 3);
        }
        cp_commit();   // one group per half: uniform numbering for wait_group 4

        if (++scur == WSTAGES) scur = 0;
        if (++s5 == WSTAGES) s5 = 0;
    }

    // Epilogue: scale + bias. d[nt][0,1] = row rl, tokens 2cl,2cl+1;
    // d[nt][2,3] = row rl+8. STG lanes rl-consecutive -> full 32B sectors.
    const int R0g = r0 + wr * 16 + rl;
    const float sc0 = ws[R0g],     bi0 = bias[R0g];
    const float sc1 = ws[R0g + 8], bi1 = bias[R0g + 8];
#pragma unroll
    for (int nt = 0; nt < 4; nt++) {
        const int T = wt * 32 + nt * 8 + 2 * cl;
        out[(size_t)T * NOUT + R0g]           = d[nt][0] * sc0 + bi0;
        out[(size_t)(T + 1) * NOUT + R0g]     = d[nt][1] * sc0 + bi0;
        out[(size_t)T * NOUT + R0g + 8]       = d[nt][2] * sc1 + bi1;
        out[(size_t)(T + 1) * NOUT + R0g + 8] = d[nt][3] * sc1 + bi1;
    }
}

// ---------------------------------------------------------------------------
extern "C" void kernel_launch(void* const* d_in, const int* in_sizes, int n_in,
                              void* d_out, int out_size) {
    (void)in_sizes; (void)n_in; (void)out_size;
    const float* x    = (const float*)d_in[0];
    const int*   wpk  = (const int*)d_in[1];
    const float* wsc  = (const float*)d_in[2];
    const float* bias = (const float*)d_in[3];
    float* out = (float*)d_out;

    cudaFuncSetAttribute(qmain, cudaFuncAttributeMaxDynamicSharedMemorySize, SMEM_TOTAL);
    convert_x<<<512, 256>>>(x);                               // 131072 threads
    qmain<<<GRID_N, 512, SMEM_TOTAL>>>(wpk, wsc, bias, out);  // 112 CTAs, one wave
}

// round 12
// speedup vs baseline: 1.4998x; 1.4998x over previous
#include <cuda_runtime.h>
#include <cuda_fp16.h>
#include <cstdint>

// ---------------------------------------------------------------------------
// Problem constants
// ---------------------------------------------------------------------------
#define M_TOK   64
#define KDIM    8192
#define NOUT    14336
#define KW      (KDIM / 2)          // 4096 int32 per output row
#define NTILE   128
#define GRID_N  (NOUT / NTILE)      // 112 CTAs = one wave

// x (fp16, k-permuted + bank-swizzled) staged per 64-k chunk: 128 chunks x 8KB
__device__ __align__(16) unsigned char g_ximg[(size_t)M_TOK * KDIM * 2];  // 1 MB

// ---------------------------------------------------------------------------
// Helpers
// ---------------------------------------------------------------------------
__device__ __forceinline__ void cp16(uint32_t saddr, const void* g) {
    asm volatile("cp.async.cg.shared.global [%0], [%1], 16;" :: "r"(saddr), "l"(g));
}
__device__ __forceinline__ void cp_commit() {
    asm volatile("cp.async.commit_group;" ::: "memory");
}
__device__ __forceinline__ void pf_l2(const void* g) {
    asm volatile("prefetch.global.L2 [%0];" :: "l"(g));
}
__device__ __forceinline__ uint2 lds64(uint32_t addr) {
    uint2 r;
    asm volatile("ld.shared.v2.u32 {%0,%1}, [%2];" : "=r"(r.x), "=r"(r.y) : "r"(addr));
    return r;
}
__device__ __forceinline__ void mma16816(float* d, uint32_t a0, uint32_t a1,
                                         uint32_t a2, uint32_t a3,
                                         uint32_t b0, uint32_t b1) {
    asm volatile(
        "mma.sync.aligned.m16n8k16.row.col.f32.f16.f16.f32 "
        "{%0,%1,%2,%3}, {%4,%5,%6,%7}, {%8,%9}, {%0,%1,%2,%3};"
        : "+f"(d[0]), "+f"(d[1]), "+f"(d[2]), "+f"(d[3])
        : "r"(a0), "r"(a1), "r"(a2), "r"(a3), "r"(b0), "r"(b1));
}

// int4-pair dequant: one int32 (value 0..255; lo nibble = even k) -> f16x2 {qlo,qhi}.
// lo half = 0x6408 ^ nibLo = 1032 + qlo (exact); HSUB2 by 1032 -> exact signed int4.
__device__ __forceinline__ uint32_t dq2(uint32_t v) {
    uint32_t t = (v & 0xFu) ^ 0x64086408u;
    uint32_t p = t ^ ((v << 12) & 0x000F0000u);
    __half2 hp = *reinterpret_cast<__half2*>(&p);
    __half2 r = __hsub2(hp, __half2half2(__ushort_as_half((unsigned short)0x6408)));
    return *reinterpret_cast<uint32_t*>(&r);
}

// ---------------------------------------------------------------------------
// Pre-kernel: x [64,8192] f32 -> f16 with the k-permutation + LDS swizzle baked in.
// Chunk cc covers physical k [cc*64, cc*64+64). Granule q (q = 4c+s, c=q>>2, s=q&3)
// stores 4 halves = physical k {8c+2s, 8c+2s+1, 32+8c+2s, 33+8c+2s} at byte offset
// tok*128 + ((q ^ (tok&7)) * 8) inside the 8KB chunk tile.
// ---------------------------------------------------------------------------
__global__ void convert_x(const float* __restrict__ x) {
    int tg  = blockIdx.x * 256 + threadIdx.x;    // 131072 threads
    int cc  = tg >> 10;
    int rem = tg & 1023;
    int tok = rem >> 4;
    int q   = rem & 15;
    int c = q >> 2, s = q & 3;
    int k0 = cc * 64 + 8 * c + 2 * s;
    float2 v0 = *reinterpret_cast<const float2*>(x + (size_t)tok * KDIM + k0);
    float2 v1 = *reinterpret_cast<const float2*>(x + (size_t)tok * KDIM + k0 + 32);
    __half2 h0 = __floats2half2_rn(v0.x, v0.y);
    __half2 h1 = __floats2half2_rn(v1.x, v1.y);
    uint2 st;
    st.x = *reinterpret_cast<uint32_t*>(&h0);
    st.y = *reinterpret_cast<uint32_t*>(&h1);
    *reinterpret_cast<uint2*>(g_ximg + (size_t)cc * 8192 + tok * 128 +
                              ((q ^ (tok & 7)) << 3)) = st;
}

// ---------------------------------------------------------------------------
// Main kernel: identical to the 94.9us R8 engine (CTA = 128 rows x 64 tokens,
// 256 threads / 8 row-warps, weights gmem->registers with 4-buffer distance-3
// prefetch, x via 2-stage cp.async ring) PLUS a rolling L2 prefetch stream:
// each (row, half) weight line (128B, aligned) is prefetched to L2 eight
// half-chunks before its LDG, converting the MLP-limited weight loads from
// DRAM-latency-bound (~577cyc) to L2-latency-bound (~250cyc).
// ---------------------------------------------------------------------------
__global__ __launch_bounds__(256, 1)
void qmain(const int* __restrict__ wp, const float* __restrict__ ws,
           const float* __restrict__ bias, float* __restrict__ out) {
    __shared__ __align__(16) unsigned char sB[2][16384];

    const int tid  = threadIdx.x;
    const int lane = tid & 31, wr = tid >> 5;         // wr 0..7 = row-warp
    const int rl = lane >> 2, cl = lane & 3;
    const int r0 = blockIdx.x * NTILE;

    const uint32_t sb = (uint32_t)__cvta_generic_to_shared(&sB[0][0]);

    // weight row pointers [rh]; thread owns int32s starting at 4*cl within a row
    const int* wptr[2];
#pragma unroll
    for (int rh = 0; rh < 2; rh++)
        wptr[rh] = wp + (size_t)(r0 + wr * 16 + rh * 8 + rl) * KW + 4 * cl;

    // L2-prefetch base: thread covers row (tid&127), half parity (tid>>7)
    const int* pfb = wp + (size_t)(r0 + (tid & 127)) * KW + (tid >> 7) * 32;

    // B-fragment smem addresses: token = nt*8 + rl (all 64 tokens per warp)
    uint32_t baddr[8];
#pragma unroll
    for (int nt = 0; nt < 8; nt++)
        baddr[nt] = sb + (uint32_t)(nt * 8 + rl) * 128;
    uint32_t gq[4];
#pragma unroll
    for (int s = 0; s < 4; s++)
        gq[s] = (uint32_t)(((4 * cl + s) ^ rl) << 3);

    // LOADW: half-chunk h -> buffer W[rh][lo/hi]; guarded for tail
#define LOADW(W, h_) do {                                                       \
        if ((h_) < 128) {                                                       \
            _Pragma("unroll")                                                   \
            for (int rh_ = 0; rh_ < 2; rh_++) {                                 \
                const int* p_ = wptr[rh_] + (h_) * 32;                          \
                W[rh_][0] = *reinterpret_cast<const uint4*>(p_);                \
                W[rh_][1] = *reinterpret_cast<const uint4*>(p_ + 16);           \
            }                                                                   \
        } } while (0)

    // PF2: prefetch the two halves {hb, hb+1}; this thread takes hb + (tid>>7)
#define PF2(hb_) do {                                                           \
        const int hp_ = (hb_);                                                  \
        if (hp_ + 1 < 128) pf_l2(pfb + (size_t)hp_ * 32);                       \
    } while (0)

#define COMP4(u4, s_) ((s_) == 0 ? (u4).x : (s_) == 1 ? (u4).y : (s_) == 2 ? (u4).z : (u4).w)

#define COMPUTE(W, sx_) do {                                                    \
        _Pragma("unroll")                                                       \
        for (int s_ = 0; s_ < 4; s_++) {                                        \
            uint32_t a0 = dq2(COMP4(W[0][0], s_));                              \
            uint32_t a1 = dq2(COMP4(W[1][0], s_));                              \
            uint32_t a2 = dq2(COMP4(W[0][1], s_));                              \
            uint32_t a3 = dq2(COMP4(W[1][1], s_));                              \
            _Pragma("unroll")                                                   \
            for (int nt_ = 0; nt_ < 8; nt_++) {                                 \
                uint2 b_ = lds64(baddr[nt_] + (sx_) + gq[s_]);                  \
                mma16816(d[nt_], a0, a1, a2, a3, b_.x, b_.y);                   \
            }                                                                   \
        } } while (0)

#define ISSUE_X(it_, slot_) do {                                               \
        const unsigned char* xg_ = g_ximg + (size_t)(it_) * 16384 + tid * 64;  \
        const uint32_t xd_ = sb + (uint32_t)(slot_) * 16384u + (uint32_t)tid * 64; \
        cp16(xd_,      xg_);      cp16(xd_ + 16, xg_ + 16);                    \
        cp16(xd_ + 32, xg_ + 32); cp16(xd_ + 48, xg_ + 48);                    \
    } while (0)

    uint4 W0[2][2], W1[2][2], W2[2][2], W3[2][2];
    float d[8][4] = {};

    // Prologue: prefetch halves 0..7 to L2 (2 lines/thread covers 4 halves;
    // issue both parities), then weight half-chunks 0..2 into registers;
    // x stages 0 and 1 in flight.
    PF2(0); PF2(2); PF2(4); PF2(6);
    LOADW(W0, 0);
    LOADW(W1, 1);
    LOADW(W2, 2);
    ISSUE_X(0, 0); cp_commit();
    ISSUE_X(1, 1); cp_commit();

    for (int p = 0; p < 32; p++) {
        // ---- iteration it = 2p (x stage 0; halves 4p, 4p+1) ----
        asm volatile("cp.async.wait_group 1;" ::: "memory");
        __syncthreads();
        PF2(4 * p + 8);                 // L2-prefetch halves 4p+8, 4p+9
        LOADW(W3, 4 * p + 3);
        COMPUTE(W0, 0u);
        LOADW(W0, 4 * p + 4);
        COMPUTE(W1, 8192u);
        __syncthreads();
        if (2 * p + 2 < 64) ISSUE_X(2 * p + 2, 0);
        cp_commit();

        // ---- iteration it = 2p+1 (x stage 1; halves 4p+2, 4p+3) ----
        asm volatile("cp.async.wait_group 1;" ::: "memory");
        __syncthreads();
        PF2(4 * p + 10);                // L2-prefetch halves 4p+10, 4p+11
        LOADW(W1, 4 * p + 5);
        COMPUTE(W2, 16384u);
        LOADW(W2, 4 * p + 6);
        COMPUTE(W3, 16384u + 8192u);
        __syncthreads();
        if (2 * p + 3 < 64) ISSUE_X(2 * p + 3, 1);
        cp_commit();
    }

    // Epilogue: scale + bias. C frag: d[nt][0,1] = row rl, tokens 2cl,2cl+1;
    // d[nt][2,3] = row rl+8. STG lanes rl consecutive -> full 32B sectors.
    const int R0g = r0 + wr * 16 + rl;
    const float sc0 = ws[R0g],     bi0 = bias[R0g];
    const float sc1 = ws[R0g + 8], bi1 = bias[R0g + 8];
#pragma unroll
    for (int nt = 0; nt < 8; nt++) {
        const int T = nt * 8 + 2 * cl;
        out[(size_t)T * NOUT + R0g]           = d[nt][0] * sc0 + bi0;
        out[(size_t)(T + 1) * NOUT + R0g]     = d[nt][1] * sc0 + bi0;
        out[(size_t)T * NOUT + R0g + 8]       = d[nt][2] * sc1 + bi1;
        out[(size_t)(T + 1) * NOUT + R0g + 8] = d[nt][3] * sc1 + bi1;
    }
}

// ---------------------------------------------------------------------------
extern "C" void kernel_launch(void* const* d_in, const int* in_sizes, int n_in,
                              void* d_out, int out_size) {
    (void)in_sizes; (void)n_in; (void)out_size;
    const float* x    = (const float*)d_in[0];
    const int*   wpk  = (const int*)d_in[1];
    const float* wsc  = (const float*)d_in[2];
    const float* bias = (const float*)d_in[3];
    float* out = (float*)d_out;

    convert_x<<<512, 256>>>(x);                       // 131072 threads
    qmain<<<GRID_N, 256>>>(wpk, wsc, bias, out);      // 112 CTAs, one wave
}

// round 13
// speedup vs baseline: 1.5929x; 1.0620x over previous
#include <cuda_runtime.h>
#include <cuda_fp16.h>
#include <cstdint>

// ---------------------------------------------------------------------------
// Problem constants
// ---------------------------------------------------------------------------
#define M_TOK   64
#define KDIM    8192
#define NOUT    14336
#define KW      (KDIM / 2)          // 4096 int32 per output row
#define NTILE   128
#define GRID_N  (NOUT / NTILE)      // 112 CTAs = one wave

// Dynamic SMEM: per warp-group 2-stage x ring (2 x 16KB), group ring at
// grp*32768. After the mainloop the first 33KB are reused for the split-K
// reduction buffer. Total 64KB.
#define SMEM_TOTAL 65536

// x (fp16, k-permuted + bank-swizzled) staged per 64-k chunk: 128 chunks x 8KB
__device__ __align__(16) unsigned char g_ximg[(size_t)M_TOK * KDIM * 2];  // 1 MB

// ---------------------------------------------------------------------------
// Helpers
// ---------------------------------------------------------------------------
__device__ __forceinline__ void cp16(uint32_t saddr, const void* g) {
    asm volatile("cp.async.cg.shared.global [%0], [%1], 16;" :: "r"(saddr), "l"(g));
}
__device__ __forceinline__ void cp_commit() {
    asm volatile("cp.async.commit_group;" ::: "memory");
}
__device__ __forceinline__ uint2 lds64(uint32_t addr) {
    uint2 r;
    asm volatile("ld.shared.v2.u32 {%0,%1}, [%2];" : "=r"(r.x), "=r"(r.y) : "r"(addr));
    return r;
}
__device__ __forceinline__ void mma16816(float* d, uint32_t a0, uint32_t a1,
                                         uint32_t a2, uint32_t a3,
                                         uint32_t b0, uint32_t b1) {
    asm volatile(
        "mma.sync.aligned.m16n8k16.row.col.f32.f16.f16.f32 "
        "{%0,%1,%2,%3}, {%4,%5,%6,%7}, {%8,%9}, {%0,%1,%2,%3};"
        : "+f"(d[0]), "+f"(d[1]), "+f"(d[2]), "+f"(d[3])
        : "r"(a0), "r"(a1), "r"(a2), "r"(a3), "r"(b0), "r"(b1));
}

// int4-pair dequant: one int32 (value 0..255; lo nibble = even k) -> f16x2 {qlo,qhi}.
// lo half = 0x6408 ^ nibLo = 1032 + qlo (exact); HSUB2 by 1032 -> exact signed int4.
__device__ __forceinline__ uint32_t dq2(uint32_t v) {
    uint32_t t = (v & 0xFu) ^ 0x64086408u;
    uint32_t p = t ^ ((v << 12) & 0x000F0000u);
    __half2 hp = *reinterpret_cast<__half2*>(&p);
    __half2 r = __hsub2(hp, __half2half2(__ushort_as_half((unsigned short)0x6408)));
    return *reinterpret_cast<uint32_t*>(&r);
}

// ---------------------------------------------------------------------------
// Pre-kernel: x [64,8192] f32 -> f16 with the k-permutation + LDS swizzle baked in.
// Chunk cc covers physical k [cc*64, cc*64+64). Granule q (q = 4c+s, c=q>>2, s=q&3)
// stores 4 halves = physical k {8c+2s, 8c+2s+1, 32+8c+2s, 33+8c+2s} at byte offset
// tok*128 + ((q ^ (tok&7)) * 8) inside the 8KB chunk tile.
// ---------------------------------------------------------------------------
__global__ void convert_x(const float* __restrict__ x) {
    int tg  = blockIdx.x * 256 + threadIdx.x;    // 131072 threads
    int cc  = tg >> 10;
    int rem = tg & 1023;
    int tok = rem >> 4;
    int q   = rem & 15;
    int c = q >> 2, s = q & 3;
    int k0 = cc * 64 + 8 * c + 2 * s;
    float2 v0 = *reinterpret_cast<const float2*>(x + (size_t)tok * KDIM + k0);
    float2 v1 = *reinterpret_cast<const float2*>(x + (size_t)tok * KDIM + k0 + 32);
    __half2 h0 = __floats2half2_rn(v0.x, v0.y);
    __half2 h1 = __floats2half2_rn(v1.x, v1.y);
    uint2 st;
    st.x = *reinterpret_cast<uint32_t*>(&h0);
    st.y = *reinterpret_cast<uint32_t*>(&h1);
    *reinterpret_cast<uint2*>(g_ximg + (size_t)cc * 8192 + tok * 128 +
                              ((q ^ (tok & 7)) << 3)) = st;
}

// ---------------------------------------------------------------------------
// Main kernel: CTA = 128 out-rows x 64 tokens, 512 threads / 16 warps,
// SPLIT-K across two warp-groups: group g (warps 8g..8g+7) owns
// k in [g*4096, (g+1)*4096). Each group is the proven R8 engine (8 row-warps
// of 16 rows x 64 tokens; weights gmem->regs->dq2->A frags with 2-buffer
// distance-1 prefetch; private 2-stage cp.async x ring). Total per-SM
// instruction count is unchanged vs R8/R12 (no duplicated dequant), but
// warps/SMSP doubles 2->4, covering the short-latency LDS/dq2/HMMA chains
// that pinned issue at 24%. Epilogue: group 1 -> SMEM partials, group 0
// adds + scale/bias + STG.
// ---------------------------------------------------------------------------
__global__ __launch_bounds__(512, 1)
void qmain(const int* __restrict__ wp, const float* __restrict__ ws,
           const float* __restrict__ bias, float* __restrict__ out) {
    extern __shared__ __align__(16) unsigned char smem[];

    const int tid  = threadIdx.x;
    const int lane = tid & 31, warp = tid >> 5;       // warp 0..15
    const int grp  = warp >> 3;                       // 0,1: k-split group
    const int wg   = warp & 7;                        // row-warp within group
    const int rl = lane >> 2, cl = lane & 3;
    const int tl = tid & 255;                         // thread index within group
    const int r0 = blockIdx.x * NTILE;

    const uint32_t sb = (uint32_t)__cvta_generic_to_shared(smem);
    const uint32_t ringbase = (uint32_t)grp * 32768u;

    // weight row pointers [rh]; group offset grp*2048 int32 = grp*4096 k
    const int* wptr[2];
#pragma unroll
    for (int rh = 0; rh < 2; rh++)
        wptr[rh] = wp + (size_t)(r0 + wg * 16 + rh * 8 + rl) * KW +
                   grp * (KW / 2) + 4 * cl;

    // B-fragment smem addresses: token = nt*8 + rl (all 64 tokens per warp)
    uint32_t baddr[8];
#pragma unroll
    for (int nt = 0; nt < 8; nt++)
        baddr[nt] = sb + ringbase + (uint32_t)(nt * 8 + rl) * 128;
    uint32_t gq[4];
#pragma unroll
    for (int s = 0; s < 4; s++)
        gq[s] = (uint32_t)(((4 * cl + s) ^ rl) << 3);

    // LOADW: local half-chunk h (0..63) -> buffer; guarded for the tail
#define LOADW(W, h_) do {                                                       \
        if ((h_) < 64) {                                                        \
            _Pragma("unroll")                                                   \
            for (int rh_ = 0; rh_ < 2; rh_++) {                                 \
                const int* p_ = wptr[rh_] + (h_) * 32;                          \
                W[rh_][0] = *reinterpret_cast<const uint4*>(p_);                \
                W[rh_][1] = *reinterpret_cast<const uint4*>(p_ + 16);           \
            }                                                                   \
        } } while (0)

#define COMP4(u4, s_) ((s_) == 0 ? (u4).x : (s_) == 1 ? (u4).y : (s_) == 2 ? (u4).z : (u4).w)

#define COMPUTE(W, sx_) do {                                                    \
        _Pragma("unroll")                                                       \
        for (int s_ = 0; s_ < 4; s_++) {                                        \
            uint32_t a0 = dq2(COMP4(W[0][0], s_));                              \
            uint32_t a1 = dq2(COMP4(W[1][0], s_));                              \
            uint32_t a2 = dq2(COMP4(W[0][1], s_));                              \
            uint32_t a3 = dq2(COMP4(W[1][1], s_));                              \
            _Pragma("unroll")                                                   \
            for (int nt_ = 0; nt_ < 8; nt_++) {                                 \
                uint2 b_ = lds64(baddr[nt_] + (sx_) + gq[s_]);                  \
                mma16816(d[nt_], a0, a1, a2, a3, b_.x, b_.y);                   \
            }                                                                   \
        } } while (0)

    // x iteration j (0..31) of this group = g_ximg 16KB block (grp*32 + j)
#define ISSUE_X(j_, slot_) do {                                                \
        const unsigned char* xg_ = g_ximg +                                    \
            (size_t)(grp * 32 + (j_)) * 16384 + tl * 64;                       \
        const uint32_t xd_ = sb + ringbase + (uint32_t)(slot_) * 16384u +      \
                             (uint32_t)tl * 64;                                \
        cp16(xd_,      xg_);      cp16(xd_ + 16, xg_ + 16);                    \
        cp16(xd_ + 32, xg_ + 32); cp16(xd_ + 48, xg_ + 48);                    \
    } while (0)

    uint4 W0[2][2], W1[2][2];
    float d[8][4] = {};

    // Prologue: first weight half in regs; x stages 0 and 1 in flight
    LOADW(W0, 0);
    ISSUE_X(0, 0); cp_commit();
    ISSUE_X(1, 1); cp_commit();

    for (int j = 0; j < 32; j++) {
        asm volatile("cp.async.wait_group 1;" ::: "memory");
        __syncthreads();
        const uint32_t sx = (uint32_t)(j & 1) * 16384u;

        LOADW(W1, 2 * j + 1);          // this iteration's 2nd half
        COMPUTE(W0, sx);
        LOADW(W0, 2 * j + 2);          // next iteration's 1st half (guarded)
        COMPUTE(W1, sx + 8192u);

        __syncthreads();
        if (j + 2 < 32) ISSUE_X(j + 2, j & 1);
        cp_commit();                   // uniform group numbering
    }

    // ---- split-K reduction + epilogue ----
    asm volatile("cp.async.wait_group 0;" ::: "memory");
    __syncthreads();

    // sred layout: warp wg -> 16 rows x 64 tokens, row stride 65 floats (pad)
    float* sred = reinterpret_cast<float*>(smem);
    if (grp == 1) {
#pragma unroll
        for (int nt = 0; nt < 8; nt++) {
            const int T = nt * 8 + 2 * cl;
            float* b0 = sred + wg * 1040 + rl * 65 + T;
            float* b1 = sred + wg * 1040 + (rl + 8) * 65 + T;
            b0[0] = d[nt][0]; b0[1] = d[nt][1];
            b1[0] = d[nt][2]; b1[1] = d[nt][3];
        }
    }
    __syncthreads();
    if (grp == 0) {
        const int R0g = r0 + wg * 16 + rl;
        const float sc0 = ws[R0g],     bi0 = bias[R0g];
        const float sc1 = ws[R0g + 8], bi1 = bias[R0g + 8];
#pragma unroll
        for (int nt = 0; nt < 8; nt++) {
            const int T = nt * 8 + 2 * cl;
            const float* b0 = sred + wg * 1040 + rl * 65 + T;
            const float* b1 = sred + wg * 1040 + (rl + 8) * 65 + T;
            out[(size_t)T * NOUT + R0g]           = (d[nt][0] + b0[0]) * sc0 + bi0;
            out[(size_t)(T + 1) * NOUT + R0g]     = (d[nt][1] + b0[1]) * sc0 + bi0;
            out[(size_t)T * NOUT + R0g + 8]       = (d[nt][2] + b1[0]) * sc1 + bi1;
            out[(size_t)(T + 1) * NOUT + R0g + 8] = (d[nt][3] + b1[1]) * sc1 + bi1;
        }
    }
}

// ---------------------------------------------------------------------------
extern "C" void kernel_launch(void* const* d_in, const int* in_sizes, int n_in,
                              void* d_out, int out_size) {
    (void)in_sizes; (void)n_in; (void)out_size;
    const float* x    = (const float*)d_in[0];
    const int*   wpk  = (const int*)d_in[1];
    const float* wsc  = (const float*)d_in[2];
    const float* bias = (const float*)d_in[3];
    float* out = (float*)d_out;

    cudaFuncSetAttribute(qmain, cudaFuncAttributeMaxDynamicSharedMemorySize, SMEM_TOTAL);
    convert_x<<<512, 256>>>(x);                               // 131072 threads
    qmain<<<GRID_N, 512, SMEM_TOTAL>>>(wpk, wsc, bias, out);  // 112 CTAs, one wave
}

// round 14
// speedup vs baseline: 1.7992x; 1.1295x over previous
#include <cuda_runtime.h>
#include <cuda_fp16.h>
#include <cstdint>

// ---------------------------------------------------------------------------
// Problem constants
// ---------------------------------------------------------------------------
#define M_TOK   64
#define KDIM    8192
#define NOUT    14336
#define KW      (KDIM / 2)          // 4096 int32 per output row
#define NTILE   128
#define GRID_N  (NOUT / NTILE)      // 112 CTAs = one wave

// Dynamic SMEM: per warp-group 2-stage x ring (2 x 16KB) at grp*32768;
// mbarriers at 65536; first 33KB reused for split-K reduction after mainloop.
#define MBAR_OFF 65536
#define SMEM_TOTAL 65664

// x (fp16, k-permuted + bank-swizzled) staged per 64-k chunk: 128 chunks x 8KB
__device__ __align__(16) unsigned char g_ximg[(size_t)M_TOK * KDIM * 2];  // 1 MB

// ---------------------------------------------------------------------------
// Helpers
// ---------------------------------------------------------------------------
__device__ __forceinline__ uint2 lds64(uint32_t addr) {
    uint2 r;
    asm volatile("ld.shared.v2.u32 {%0,%1}, [%2];" : "=r"(r.x), "=r"(r.y) : "r"(addr));
    return r;
}
__device__ __forceinline__ void mma16816(float* d, uint32_t a0, uint32_t a1,
                                         uint32_t a2, uint32_t a3,
                                         uint32_t b0, uint32_t b1) {
    asm volatile(
        "mma.sync.aligned.m16n8k16.row.col.f32.f16.f16.f32 "
        "{%0,%1,%2,%3}, {%4,%5,%6,%7}, {%8,%9}, {%0,%1,%2,%3};"
        : "+f"(d[0]), "+f"(d[1]), "+f"(d[2]), "+f"(d[3])
        : "r"(a0), "r"(a1), "r"(a2), "r"(a3), "r"(b0), "r"(b1));
}

#define MBARRIER_INIT(addr, cnt) \
    asm volatile("mbarrier.init.shared.b64 [%0], %1;" :: "r"(addr), "r"(cnt) : "memory")
#define MBARRIER_EXPECT_TX(addr, bytes) \
    asm volatile("mbarrier.arrive.expect_tx.shared.b64 _, [%0], %1;" \
                 :: "r"(addr), "r"(bytes) : "memory")
#define FENCE_PROXY_ASYNC() \
    asm volatile("fence.proxy.async.shared::cta;" ::: "memory")
#define BULK_G2S(dst, src, bytes, mbar) \
    asm volatile("cp.async.bulk.shared::cluster.global.mbarrier::complete_tx::bytes " \
                 "[%0], [%1], %2, [%3];" \
                 :: "r"(dst), "l"(src), "r"(bytes), "r"(mbar) : "memory")
#define MBARRIER_WAIT_PARITY(addr, parity) do {                                          \
    uint32_t _m = (addr), _p = (parity), _done;                                          \
    asm volatile("{ .reg .pred p; mbarrier.try_wait.parity.acquire.cta.shared::cta.b64 " \
                 "p, [%1], %2; selp.b32 %0, 1, 0, p; }"                                  \
                 : "=r"(_done) : "r"(_m), "r"(_p) : "memory");                           \
    if (!_done) {                                                                        \
        asm volatile("{ .reg .pred P1; WL_%=: "                                          \
                     "mbarrier.try_wait.parity.acquire.cta.shared::cta.b64 P1, [%0], %1, 0x989680; " \
                     "@P1 bra.uni WD_%=; bra.uni WL_%=; WD_%=: }"                        \
                     :: "r"(_m), "r"(_p) : "memory");                                    \
    } } while (0)

// int4-pair dequant: one int32 (value 0..255; lo nibble = even k) -> f16x2 {qlo,qhi}.
// lo half = 0x6408 ^ nibLo = 1032 + qlo (exact); HSUB2 by 1032 -> exact signed int4.
__device__ __forceinline__ uint32_t dq2(uint32_t v) {
    uint32_t t = (v & 0xFu) ^ 0x64086408u;
    uint32_t p = t ^ ((v << 12) & 0x000F0000u);
    __half2 hp = *reinterpret_cast<__half2*>(&p);
    __half2 r = __hsub2(hp, __half2half2(__ushort_as_half((unsigned short)0x6408)));
    return *reinterpret_cast<uint32_t*>(&r);
}

// ---------------------------------------------------------------------------
// Pre-kernel: x [64,8192] f32 -> f16 with the k-permutation + LDS swizzle baked in.
// Chunk cc covers physical k [cc*64, cc*64+64). Granule q (q = 4c+s, c=q>>2, s=q&3)
// stores 4 halves = physical k {8c+2s, 8c+2s+1, 32+8c+2s, 33+8c+2s} at byte offset
// tok*128 + ((q ^ (tok&7)) * 8) inside the 8KB chunk tile.
// ---------------------------------------------------------------------------
__global__ void convert_x(const float* __restrict__ x) {
    int tg  = blockIdx.x * 256 + threadIdx.x;    // 131072 threads
    int cc  = tg >> 10;
    int rem = tg & 1023;
    int tok = rem >> 4;
    int q   = rem & 15;
    int c = q >> 2, s = q & 3;
    int k0 = cc * 64 + 8 * c + 2 * s;
    float2 v0 = *reinterpret_cast<const float2*>(x + (size_t)tok * KDIM + k0);
    float2 v1 = *reinterpret_cast<const float2*>(x + (size_t)tok * KDIM + k0 + 32);
    __half2 h0 = __floats2half2_rn(v0.x, v0.y);
    __half2 h1 = __floats2half2_rn(v1.x, v1.y);
    uint2 st;
    st.x = *reinterpret_cast<uint32_t*>(&h0);
    st.y = *reinterpret_cast<uint32_t*>(&h1);
    *reinterpret_cast<uint2*>(g_ximg + (size_t)cc * 8192 + tok * 128 +
                              ((q ^ (tok & 7)) << 3)) = st;
}

// ---------------------------------------------------------------------------
// Main kernel: CTA = 128 out-rows x 64 tokens, 512 threads / 16 warps,
// SPLIT-K across two warp-groups (group g owns k in [g*4096, (g+1)*4096)),
// each group = the R8 engine (8 row-warps x 16 rows x 64 tokens; weights
// gmem->regs->dq2 with 2-buffer distance-1 prefetch). x is staged by
// cp.async.bulk (ONE instruction per 16KB stage, mbarrier completion) —
// removing the 8-cyc/op LDGSTS issue tax (131K cyc/SMSP in R13) that
// oversubscribed the LSU and pinned issue at 27%.
// ---------------------------------------------------------------------------
__global__ __launch_bounds__(512, 1)
void qmain(const int* __restrict__ wp, const float* __restrict__ ws,
           const float* __restrict__ bias, float* __restrict__ out) {
    extern __shared__ __align__(16) unsigned char smem[];

    const int tid  = threadIdx.x;
    const int lane = tid & 31, warp = tid >> 5;       // warp 0..15
    const int grp  = warp >> 3;                       // 0,1: k-split group
    const int wg   = warp & 7;                        // row-warp within group
    const int rl = lane >> 2, cl = lane & 3;
    const int tl = tid & 255;                         // thread index within group
    const int r0 = blockIdx.x * NTILE;

    const uint32_t sb = (uint32_t)__cvta_generic_to_shared(smem);
    const uint32_t ringbase = (uint32_t)grp * 32768u;
    const uint32_t mb0 = sb + MBAR_OFF + (uint32_t)grp * 32u;       // stage 0 barrier
    const uint32_t mb1 = mb0 + 16u;                                 // stage 1 barrier

    // weight row pointers [rh]; group offset grp*2048 int32 = grp*4096 k
    const int* wptr[2];
#pragma unroll
    for (int rh = 0; rh < 2; rh++)
        wptr[rh] = wp + (size_t)(r0 + wg * 16 + rh * 8 + rl) * KW +
                   grp * (KW / 2) + 4 * cl;

    // B-fragment smem addresses: token = nt*8 + rl (all 64 tokens per warp)
    uint32_t baddr[8];
#pragma unroll
    for (int nt = 0; nt < 8; nt++)
        baddr[nt] = sb + ringbase + (uint32_t)(nt * 8 + rl) * 128;
    uint32_t gq[4];
#pragma unroll
    for (int s = 0; s < 4; s++)
        gq[s] = (uint32_t)(((4 * cl + s) ^ rl) << 3);

    // LOADW: local half-chunk h (0..63) -> buffer; guarded for the tail
#define LOADW(W, h_) do {                                                       \
        if ((h_) < 64) {                                                        \
            _Pragma("unroll")                                                   \
            for (int rh_ = 0; rh_ < 2; rh_++) {                                 \
                const int* p_ = wptr[rh_] + (h_) * 32;                          \
                W[rh_][0] = *reinterpret_cast<const uint4*>(p_);                \
                W[rh_][1] = *reinterpret_cast<const uint4*>(p_ + 16);           \
            }                                                                   \
        } } while (0)

#define COMP4(u4, s_) ((s_) == 0 ? (u4).x : (s_) == 1 ? (u4).y : (s_) == 2 ? (u4).z : (u4).w)

#define COMPUTE(W, sx_) do {                                                    \
        _Pragma("unroll")                                                       \
        for (int s_ = 0; s_ < 4; s_++) {                                        \
            uint32_t a0 = dq2(COMP4(W[0][0], s_));                              \
            uint32_t a1 = dq2(COMP4(W[1][0], s_));                              \
            uint32_t a2 = dq2(COMP4(W[0][1], s_));                              \
            uint32_t a3 = dq2(COMP4(W[1][1], s_));                              \
            _Pragma("unroll")                                                   \
            for (int nt_ = 0; nt_ < 8; nt_++) {                                 \
                uint2 b_ = lds64(baddr[nt_] + (sx_) + gq[s_]);                  \
                mma16816(d[nt_], a0, a1, a2, a3, b_.x, b_.y);                   \
            }                                                                   \
        } } while (0)

    // x iteration j (0..31) of this group = g_ximg 16KB block (grp*32 + j)
#define ISSUE_BULK(j_, slot_) do {                                             \
        const unsigned char* xg_ = g_ximg + (size_t)(grp * 32 + (j_)) * 16384; \
        const uint32_t xd_ = sb + ringbase + (uint32_t)(slot_) * 16384u;       \
        const uint32_t mb_ = (slot_) ? mb1 : mb0;                              \
        MBARRIER_EXPECT_TX(mb_, 16384u);                                       \
        BULK_G2S(xd_, xg_, 16384u, mb_);                                       \
    } while (0)

    uint4 W0[2][2], W1[2][2];
    float d[8][4] = {};

    // Barrier init (one thread per group), then prologue bulk fills
    if (tl == 0) { MBARRIER_INIT(mb0, 1); MBARRIER_INIT(mb1, 1); }
    __syncthreads();
    if (tl == 0) {
        FENCE_PROXY_ASYNC();
        ISSUE_BULK(0, 0);
        ISSUE_BULK(1, 1);
    }

    // First weight half in registers
    LOADW(W0, 0);

    for (int j = 0; j < 32; j++) {
        // Wait for stage (j&1) fill number (j>>1): parity = (j>>1)&1
        MBARRIER_WAIT_PARITY((j & 1) ? mb1 : mb0, (uint32_t)((j >> 1) & 1));
        const uint32_t sx = (uint32_t)(j & 1) * 16384u;

        LOADW(W1, 2 * j + 1);          // this iteration's 2nd half
        COMPUTE(W0, sx);
        LOADW(W0, 2 * j + 2);          // next iteration's 1st half (guarded)
        COMPUTE(W1, sx + 8192u);

        __syncthreads();               // all threads done reading stage j&1
        if (tl == 0 && j + 2 < 32) ISSUE_BULK(j + 2, j & 1);
    }

    // ---- split-K reduction + epilogue ----
    __syncthreads();

    // sred layout: warp wg -> 16 rows x 64 tokens, row stride 65 floats (pad)
    float* sred = reinterpret_cast<float*>(smem);
    if (grp == 1) {
#pragma unroll
        for (int nt = 0; nt < 8; nt++) {
            const int T = nt * 8 + 2 * cl;
            float* b0 = sred + wg * 1040 + rl * 65 + T;
            float* b1 = sred + wg * 1040 + (rl + 8) * 65 + T;
            b0[0] = d[nt][0]; b0[1] = d[nt][1];
            b1[0] = d[nt][2]; b1[1] = d[nt][3];
        }
    }
    __syncthreads();
    if (grp == 0) {
        const int R0g = r0 + wg * 16 + rl;
        const float sc0 = ws[R0g],     bi0 = bias[R0g];
        const float sc1 = ws[R0g + 8], bi1 = bias[R0g + 8];
#pragma unroll
        for (int nt = 0; nt < 8; nt++) {
            const int T = nt * 8 + 2 * cl;
            const float* b0 = sred + wg * 1040 + rl * 65 + T;
            const float* b1 = sred + wg * 1040 + (rl + 8) * 65 + T;
            out[(size_t)T * NOUT + R0g]           = (d[nt][0] + b0[0]) * sc0 + bi0;
            out[(size_t)(T + 1) * NOUT + R0g]     = (d[nt][1] + b0[1]) * sc0 + bi0;
            out[(size_t)T * NOUT + R0g + 8]       = (d[nt][2] + b1[0]) * sc1 + bi1;
            out[(size_t)(T + 1) * NOUT + R0g + 8] = (d[nt][3] + b1[1]) * sc1 + bi1;
        }
    }
}

// ---------------------------------------------------------------------------
extern "C" void kernel_launch(void* const* d_in, const int* in_sizes, int n_in,
                              void* d_out, int out_size) {
    (void)in_sizes; (void)n_in; (void)out_size;
    const float* x    = (const float*)d_in[0];
    const int*   wpk  = (const int*)d_in[1];
    const float* wsc  = (const float*)d_in[2];
    const float* bias = (const float*)d_in[3];
    float* out = (float*)d_out;

    cudaFuncSetAttribute(qmain, cudaFuncAttributeMaxDynamicSharedMemorySize, SMEM_TOTAL);
    convert_x<<<512, 256>>>(x);                               // 131072 threads
    qmain<<<GRID_N, 512, SMEM_TOTAL>>>(wpk, wsc, bias, out);  // 112 CTAs, one wave
}